// round 5
// baseline (speedup 1.0000x reference)
#include <cuda_runtime.h>

#define BATCH 4
#define CH    64
#define HH    128
#define WW    128
#define HW    (HH*WW)
#define J18   18
#define CK    576   /* CH*9 */

// Device-global scratch
__device__ float g_xt[BATCH*HW*CH];    // x transposed to [b][h][w][c]
__device__ float g_off[BATCH*HW*J18];  // offsets [b][h][w][j]
__device__ float g_wT[CK*CH];          // W repacked: [tap*64+c][o]

__device__ __forceinline__ void fma2(unsigned long long& a,
                                     unsigned long long b,
                                     unsigned long long c) {
    asm("fma.rn.f32x2 %0, %1, %2, %0;" : "+l"(a) : "l"(b), "l"(c));
}
__device__ __forceinline__ unsigned long long dup2(float v) {
    unsigned long long r;
    asm("mov.b64 %0, {%1,%1};" : "=l"(r) : "f"(v));
    return r;
}
__device__ __forceinline__ unsigned long long pack2(float a, float b) {
    unsigned long long r;
    asm("mov.b64 %0, {%1,%2};" : "=l"(r) : "f"(a), "f"(b));
    return r;
}
__device__ __forceinline__ void unpack2(unsigned long long v, float& a, float& b) {
    asm("mov.b64 {%0,%1}, %2;" : "=f"(a), "=f"(b) : "l"(v));
}

// ---------------------------------------------------------------------------
// Repack main weight: [o][c][tap] -> [tap*64+c][o]
// ---------------------------------------------------------------------------
__global__ void k_prep_wT(const float* __restrict__ weight) {
    int i = blockIdx.x * 256 + threadIdx.x;
    if (i >= CK * CH) return;
    int o   = i & 63;
    int ckp = i >> 6;          // tap*64 + c
    int tap = ckp >> 6, c = ckp & 63;
    g_wT[ckp * 64 + o] = weight[(o * CH + c) * 9 + tap];
}

// ---------------------------------------------------------------------------
// NCHW -> NHWC transpose of x
// ---------------------------------------------------------------------------
__global__ void k_transpose(const float* __restrict__ x) {
    __shared__ float t[32][33];
    int b  = blockIdx.z;
    int c0 = blockIdx.y * 32;
    int p0 = blockIdx.x * 32;
    int tx = threadIdx.x, ty = threadIdx.y;   // 32 x 8
    const float* xb = x + (size_t)b * CH * HW;
#pragma unroll
    for (int i = 0; i < 4; i++)
        t[ty + i * 8][tx] = xb[(c0 + ty + i * 8) * HW + p0 + tx];
    __syncthreads();
    float* dst = g_xt + (size_t)b * HW * CH;
#pragma unroll
    for (int i = 0; i < 4; i++)
        dst[(p0 + ty + i * 8) * CH + c0 + tx] = t[tx][ty + i * 8];
}

// ---------------------------------------------------------------------------
// Offset conv: Conv2d(64 -> 18, 3x3, pad 1) on NCHW x, f32x2 accumulation.
// ---------------------------------------------------------------------------
__global__ void k_offconv(const float* __restrict__ x,
                          const float* __restrict__ w_off,
                          const float* __restrict__ b_off) {
    __shared__ __align__(16) float ws[CH * 9 * 20];   // 46080 B
    int tid = threadIdx.y * 32 + threadIdx.x;
    for (int i = tid; i < CH * 9 * J18; i += 128) {
        int j = i % 18; int t = i / 18; int tap = t % 9; int c = t / 9;
        ws[(c * 9 + tap) * 20 + j] = w_off[(j * CH + c) * 9 + tap];
    }
    __syncthreads();

    int b = blockIdx.z;
    int h = blockIdx.y * 4 + threadIdx.y;
    int w = blockIdx.x * 32 + threadIdx.x;

    unsigned long long acc2[9];
#pragma unroll
    for (int q = 0; q < 9; q++)
        acc2[q] = pack2(__ldg(b_off + 2 * q), __ldg(b_off + 2 * q + 1));

    const float* xb = x + (size_t)b * CH * HW;
    for (int c = 0; c < CH; c++) {
        const float* xc = xb + c * HW;
#pragma unroll
        for (int r = 0; r < 3; r++) {
            int y = h + r - 1;
            if ((unsigned)y < (unsigned)HH) {
                const float* xr = xc + y * WW;
                float v0 = (w >= 1)      ? __ldg(xr + w - 1) : 0.f;
                float v1 =                 __ldg(xr + w);
                float v2 = (w < WW - 1)  ? __ldg(xr + w + 1) : 0.f;
                const float* wsr = ws + (c * 9 + r * 3) * 20;
#pragma unroll
                for (int s = 0; s < 3; s++) {
                    float val = (s == 0) ? v0 : ((s == 1) ? v1 : v2);
                    unsigned long long vd = dup2(val);
                    const double2* wp = (const double2*)(wsr + s * 20);
                    double2 p0 = wp[0], p1 = wp[1];
                    double2 p2 = wp[2], p3 = wp[3];
                    double   p4 = *(const double*)(wsr + s * 20 + 16);
                    fma2(acc2[0], vd, __double_as_longlong(p0.x));
                    fma2(acc2[1], vd, __double_as_longlong(p0.y));
                    fma2(acc2[2], vd, __double_as_longlong(p1.x));
                    fma2(acc2[3], vd, __double_as_longlong(p1.y));
                    fma2(acc2[4], vd, __double_as_longlong(p2.x));
                    fma2(acc2[5], vd, __double_as_longlong(p2.y));
                    fma2(acc2[6], vd, __double_as_longlong(p3.x));
                    fma2(acc2[7], vd, __double_as_longlong(p3.y));
                    fma2(acc2[8], vd, __double_as_longlong(p4));
                }
            }
        }
    }

    __syncthreads();
#pragma unroll
    for (int q = 0; q < 9; q++) {
        float a, bb;
        unpack2(acc2[q], a, bb);
        ws[threadIdx.y * 576 + threadIdx.x * 18 + 2 * q]     = a;
        ws[threadIdx.y * 576 + threadIdx.x * 18 + 2 * q + 1] = bb;
    }
    __syncthreads();
    for (int i = tid; i < 4 * 576; i += 128) {
        int row = i / 576, col = i % 576;
        int h2 = blockIdx.y * 4 + row;
        g_off[((size_t)b * HW + h2 * WW + blockIdx.x * 32) * 18 + col] = ws[row * 576 + col];
    }
}

// ---------------------------------------------------------------------------
// Deformable gather + register-blocked GEMM. CTA tile = 64 o x 64 px (4x16).
// smem: S chunk [192 ck][64 px] (49KB) + precomputed gather idx/wts (18.4KB).
// 3 chunks of 3 taps x 64 channels. Thread computes 4o x 4px via f32x2.
// ---------------------------------------------------------------------------
#define SM_S_FLOATS (192 * 64)
#define N_PT 576   /* px(64) x tap(9) coord entries */
#define SMEM_DEFORM (SM_S_FLOATS * 4 + N_PT * 16 * 2)

__global__ void __launch_bounds__(256) k_deform(float* __restrict__ out) {
    extern __shared__ __align__(16) float sm[];
    float* sS   = sm;                               // [192][64]
    int4*  sIdx = (int4*)(sm + SM_S_FLOATS);        // [576] clamped linear offs
    float4* sWt = (float4*)(sm + SM_S_FLOATS + N_PT * 4); // [576] masked wts

    int b  = blockIdx.z;
    int h0 = blockIdx.y * 4, w0 = blockIdx.x * 16;
    int tid  = threadIdx.x;
    int warp = tid >> 5, lane = tid & 31;

    const float* xt = g_xt + (size_t)b * HW * CH;

    // ---- Precompute bilinear coords: entry i = tap*64 + px ----
    for (int i = tid; i < N_PT; i += 256) {
        int tap = i >> 6, px = i & 63;
        int ph = h0 + (px >> 4), pw = w0 + (px & 15);
        const float* op = g_off + ((size_t)b * HW + ph * WW + pw) * 18 + tap * 2;
        float dy = __ldg(op), dx = __ldg(op + 1);
        float py = (float)(ph + tap / 3 - 1) + dy;
        float pxf = (float)(pw + tap % 3 - 1) + dx;
        float fy = floorf(py), fx = floorf(pxf);
        int y0 = (int)fy, x0 = (int)fx;
        float ly = py - fy, lx = pxf - fx;
        float hy = 1.f - ly, hx = 1.f - lx;
        float my0 = ((unsigned)y0       < (unsigned)HH) ? 1.f : 0.f;
        float my1 = ((unsigned)(y0 + 1) < (unsigned)HH) ? 1.f : 0.f;
        float mx0 = ((unsigned)x0       < (unsigned)WW) ? 1.f : 0.f;
        float mx1 = ((unsigned)(x0 + 1) < (unsigned)WW) ? 1.f : 0.f;
        int y0c = min(max(y0, 0), HH - 1);
        int y1c = min(max(y0 + 1, 0), HH - 1);
        int x0c = min(max(x0, 0), WW - 1);
        int x1c = min(max(x0 + 1, 0), WW - 1);
        sIdx[i] = make_int4((y0c * WW + x0c) * CH, (y0c * WW + x1c) * CH,
                            (y1c * WW + x0c) * CH, (y1c * WW + x1c) * CH);
        sWt[i]  = make_float4(hy * hx * my0 * mx0, hy * lx * my0 * mx1,
                              ly * hx * my1 * mx0, ly * lx * my1 * mx1);
    }

    // ---- Thread's GEMM tile: 4 o x 4 px ----
    int o_base  = (warp & 1) * 32 + (lane & 7) * 4;
    int px_base = (warp >> 1) * 16 + (lane >> 3) * 4;
    unsigned sSsh = (unsigned)__cvta_generic_to_shared(sS + px_base);

    unsigned long long a00 = 0, a01 = 0, a10 = 0, a11 = 0;
    unsigned long long a20 = 0, a21 = 0, a30 = 0, a31 = 0;

    for (int c3 = 0; c3 < 3; c3++) {
        __syncthreads();   // phase2 of previous chunk done before overwrite
        // ---- Gather chunk: taps 3*c3 .. 3*c3+2, all 64 channels ----
        for (int t = warp; t < 96; t += 8) {
            int chalf = t & 1, q = (t >> 1) & 15, tap_l = t >> 5;
            int tap = c3 * 3 + tap_l;
            int c   = chalf * 32 + lane;
            const float* xc = xt + c;
            float rv[4];
#pragma unroll
            for (int i = 0; i < 4; i++) {
                int e = tap * 64 + q * 4 + i;
                int4   ix = sIdx[e];
                float4 wt = sWt[e];
                rv[i] = wt.x * __ldg(xc + ix.x) + wt.y * __ldg(xc + ix.y)
                      + wt.z * __ldg(xc + ix.z) + wt.w * __ldg(xc + ix.w);
            }
            int k = tap_l * 64 + c;
            *(float4*)(sS + k * 64 + q * 4) = make_float4(rv[0], rv[1], rv[2], rv[3]);
        }
        __syncthreads();

        // ---- GEMM partial over 192 k ----
        const float* wp = g_wT + (size_t)(c3 * 192) * 64 + o_base;
#pragma unroll 4
        for (int k = 0; k < 192; k++) {
            float4 wv = __ldg((const float4*)(wp + k * 64));
            unsigned long long s01, s23;
            asm("ld.shared.v2.b64 {%0,%1},[%2];"
                : "=l"(s01), "=l"(s23) : "r"(sSsh + k * 256));
            unsigned long long w0d = dup2(wv.x), w1d = dup2(wv.y);
            unsigned long long w2d = dup2(wv.z), w3d = dup2(wv.w);
            fma2(a00, w0d, s01); fma2(a01, w0d, s23);
            fma2(a10, w1d, s01); fma2(a11, w1d, s23);
            fma2(a20, w2d, s01); fma2(a21, w2d, s23);
            fma2(a30, w3d, s01); fma2(a31, w3d, s23);
        }
    }

    // ---- Write out: 4 STG.128, one per o ----
    int h = h0 + (px_base >> 4);
    int w = w0 + (px_base & 15);
    float r0, r1, r2, r3;
    float* ob = out + (((size_t)b * CH + o_base) * HH + h) * WW + w;
    unpack2(a00, r0, r1); unpack2(a01, r2, r3);
    *(float4*)(ob)               = make_float4(r0, r1, r2, r3);
    unpack2(a10, r0, r1); unpack2(a11, r2, r3);
    *(float4*)(ob + HW)          = make_float4(r0, r1, r2, r3);
    unpack2(a20, r0, r1); unpack2(a21, r2, r3);
    *(float4*)(ob + 2 * HW)      = make_float4(r0, r1, r2, r3);
    unpack2(a30, r0, r1); unpack2(a31, r2, r3);
    *(float4*)(ob + 3 * HW)      = make_float4(r0, r1, r2, r3);
}

// ---------------------------------------------------------------------------
extern "C" void kernel_launch(void* const* d_in, const int* in_sizes, int n_in,
                              void* d_out, int out_size) {
    const float* x      = (const float*)d_in[0];
    const float* w_off  = (const float*)d_in[1];
    const float* b_off  = (const float*)d_in[2];
    const float* weight = (const float*)d_in[3];
    float* out = (float*)d_out;

    cudaFuncSetAttribute(k_deform, cudaFuncAttributeMaxDynamicSharedMemorySize,
                         SMEM_DEFORM);

    k_prep_wT<<<(CK * CH + 255) / 256, 256>>>(weight);
    k_transpose<<<dim3(HW / 32, CH / 32, BATCH), dim3(32, 8)>>>(x);
    k_offconv<<<dim3(WW / 32, HH / 4, BATCH), dim3(32, 4)>>>(x, w_off, b_off);
    k_deform<<<dim3(WW / 16, HH / 4, BATCH), 256, SMEM_DEFORM>>>(out);
}